// round 1
// baseline (speedup 1.0000x reference)
#include <cuda_runtime.h>
#include <cuda_bf16.h>
#include <cstddef>

// ---------------------------------------------------------------------------
// VideoEncoder: 3x Conv3D (stride 1,2,2; pad 1) + VQ argmin + embedding gather
// Shapes:
//   video [2,3,16,128,128]
//   h1    [2,128,16,64,64]   (relu)
//   h2    [2,256,16,32,32]   (relu)
//   f     [2,512,16,16,16]
//   tokens [2,4096] (argmin over 8192 codes), embeddings [2,4096,512]
// ---------------------------------------------------------------------------

// Scratch (device globals: allocation-free rule)
__device__ float g_h1[2 * 128 * 16 * 64 * 64];   // 64 MB
__device__ float g_h2[2 * 256 * 16 * 32 * 32];   // 32 MB
__device__ float g_f [2 * 512 * 16 * 16 * 16];   // 16 MB
__device__ float g_c2[8192];
__device__ float g_ps[4 * 8192];
__device__ int   g_pi[4 * 8192];
__device__ int   g_tok[8192];

// ---------------------------------------------------------------------------
// Generic conv3d as implicit-im2col GEMM.
// Tile: 64 output channels x 32 output positions, K = CIN*27.
// 128 threads; each thread: 4 co x 4 pos accumulators.
// ---------------------------------------------------------------------------
template<int CIN, int CO, int OT, int IH, int IW, int OH, int OW, bool RELU>
__global__ void __launch_bounds__(128) conv3d_kernel(
    const float* __restrict__ x, const float* __restrict__ w,
    const float* __restrict__ bias, float* __restrict__ y)
{
    constexpr int K   = CIN * 27;
    constexpr int IT  = OT;
    constexpr int SPO = OT * OH * OW;

    __shared__ float Ws[16][64];   // [k][co]
    __shared__ float Xs[16][32];   // [k][pos]

    const int tid = threadIdx.x;
    const int tv  = tid & 15;      // co-sub group (0..15)
    const int tp  = tid >> 4;      // pos-sub group (0..7)
    const int pt  = blockIdx.x * 32;
    const int cot = blockIdx.y * 64;
    const int b   = pt / SPO;      // 32 | SPO, so whole tile shares b

    // loader-side: this thread stages k-row (tid>>3) for 4 consecutive pcols
    const int lk  = tid >> 3;
    const int lp0 = (tid & 7) * 4;
    int lt[4], lh[4], lw[4];
#pragma unroll
    for (int q = 0; q < 4; q++) {
        int p  = pt + lp0 + q;
        int sp = p - b * SPO;
        lt[q]  = sp / (OH * OW);
        int r  = sp % (OH * OW);
        lh[q]  = r / OW;
        lw[q]  = r % OW;
    }
    // store-side offsets
    int outoff[4];
#pragma unroll
    for (int j = 0; j < 4; j++) {
        int p = pt + tp * 4 + j;
        outoff[j] = p - b * SPO;
    }

    float acc[4][4];
#pragma unroll
    for (int i = 0; i < 4; i++)
#pragma unroll
        for (int j = 0; j < 4; j++) acc[i][j] = 0.f;

    const int nch = (K + 15) / 16;
    for (int c0 = 0; c0 < nch; c0++) {
        const int k0 = c0 * 16;
        // --- W tile: Ws[k][co], 1024 elems, 8 per thread
#pragma unroll
        for (int q = 0; q < 8; q++) {
            int e  = tid * 8 + q;
            int cr = e >> 4, kk = e & 15;
            int k  = k0 + kk;
            Ws[kk][cr] = (k < K) ? w[(size_t)(cot + cr) * K + k] : 0.f;
        }
        // --- X tile: gather (implicit im2col)
        {
            int k = k0 + lk;
            float4 vv = make_float4(0.f, 0.f, 0.f, 0.f);
            float* vp = (float*)&vv;
            if (k < K) {
                int ci = k / 27, tap = k - ci * 27;
                int kt = tap / 9, r9 = tap - kt * 9;
                int kh = r9 / 3,  kw = r9 - kh * 3;
                const float* xb = x + (size_t)(b * CIN + ci) * (IT * IH * IW);
#pragma unroll
                for (int q = 0; q < 4; q++) {
                    int it = lt[q] + kt - 1;
                    int ih = 2 * lh[q] + kh - 1;
                    int iw = 2 * lw[q] + kw - 1;
                    bool ok = (it >= 0) && (it < IT) && (ih >= 0) && (ih < IH)
                              && (iw >= 0) && (iw < IW);
                    vp[q] = ok ? xb[(it * IH + ih) * IW + iw] : 0.f;
                }
            }
            *(float4*)&Xs[lk][lp0] = vv;
        }
        __syncthreads();
#pragma unroll
        for (int kk = 0; kk < 16; kk++) {
            float4 xr = *(const float4*)&Xs[kk][tp * 4];
            float4 wr = *(const float4*)&Ws[kk][tv * 4];
            float xa[4] = {xr.x, xr.y, xr.z, xr.w};
            float wa[4] = {wr.x, wr.y, wr.z, wr.w};
#pragma unroll
            for (int i = 0; i < 4; i++)
#pragma unroll
                for (int j = 0; j < 4; j++)
                    acc[i][j] = fmaf(wa[i], xa[j], acc[i][j]);
        }
        __syncthreads();
    }

    // epilogue: bias + relu + store
#pragma unroll
    for (int i = 0; i < 4; i++) {
        int co = cot + tv * 4 + i;
        float bb = bias[co];
        float* yb = y + (size_t)(b * CO + co) * SPO;
#pragma unroll
        for (int j = 0; j < 4; j++) {
            float v = acc[i][j] + bb;
            if (RELU) v = fmaxf(v, 0.f);
            yb[outoff[j]] = v;
        }
    }
}

// ---------------------------------------------------------------------------
// codebook row norms: one warp per row
// ---------------------------------------------------------------------------
__global__ void __launch_bounds__(256) c2_kernel(const float* __restrict__ cb,
                                                 float* __restrict__ c2)
{
    int v    = blockIdx.x * 8 + (threadIdx.x >> 5);
    int lane = threadIdx.x & 31;
    const float* r = cb + (size_t)v * 512;
    float s = 0.f;
#pragma unroll 4
    for (int c = lane; c < 512; c += 32) { float xv = r[c]; s = fmaf(xv, xv, s); }
#pragma unroll
    for (int off = 16; off; off >>= 1) s += __shfl_down_sync(0xffffffffu, s, off);
    if (lane == 0) c2[v] = s;
}

// ---------------------------------------------------------------------------
// VQ: per 32-position tile, scan a 2048-code segment (grid.y = 4 segments),
// GEMM microkernel identical to conv. Partial (minval,minidx) per segment.
// ---------------------------------------------------------------------------
__global__ void __launch_bounds__(128) vq_kernel(
    const float* __restrict__ f, const float* __restrict__ cb,
    const float* __restrict__ c2, float* __restrict__ partS, int* __restrict__ partI)
{
    __shared__ float Cs[16][64];   // [k][v]
    __shared__ float Fs[16][32];   // [k][pos]

    const int tid = threadIdx.x;
    const int tv  = tid & 15;
    const int tp  = tid >> 4;
    const int pt  = blockIdx.x * 32;   // position tile (256 blocks)
    const int seg = blockIdx.y;        // code segment (0..3)
    const int b   = pt >> 12;          // / 4096
    const int sp0 = pt & 4095;

    float bestS[4];
    int   bestI[4];
#pragma unroll
    for (int j = 0; j < 4; j++) { bestS[j] = 3.4e38f; bestI[j] = 0; }

    const int vend = (seg + 1) * 2048;
    for (int vt = seg * 2048; vt < vend; vt += 64) {
        float acc[4][4];
#pragma unroll
        for (int i = 0; i < 4; i++)
#pragma unroll
            for (int j = 0; j < 4; j++) acc[i][j] = 0.f;

        for (int kc = 0; kc < 512; kc += 16) {
#pragma unroll
            for (int q = 0; q < 8; q++) {
                int e  = tid * 8 + q;
                int vr = e >> 4, kk = e & 15;
                Cs[kk][vr] = cb[(size_t)(vt + vr) * 512 + kc + kk];
            }
            {
                int kk = tid >> 3, pc = (tid & 7) * 4;
                *(float4*)&Fs[kk][pc] =
                    *(const float4*)&f[((size_t)b * 512 + kc + kk) * 4096 + sp0 + pc];
            }
            __syncthreads();
#pragma unroll
            for (int kk = 0; kk < 16; kk++) {
                float4 xr = *(const float4*)&Fs[kk][tp * 4];
                float4 cr = *(const float4*)&Cs[kk][tv * 4];
                float xa[4] = {xr.x, xr.y, xr.z, xr.w};
                float ca[4] = {cr.x, cr.y, cr.z, cr.w};
#pragma unroll
                for (int i = 0; i < 4; i++)
#pragma unroll
                    for (int j = 0; j < 4; j++)
                        acc[i][j] = fmaf(ca[i], xa[j], acc[i][j]);
            }
            __syncthreads();
        }
        // fold into running min:  s = ||c||^2 - 2*dot   (f^2 term is constant per pos)
#pragma unroll
        for (int i = 0; i < 4; i++) {
            int v = vt + tv * 4 + i;
            float cc = __ldg(&c2[v]);
#pragma unroll
            for (int j = 0; j < 4; j++) {
                float s = fmaf(-2.f, acc[i][j], cc);
                if (s < bestS[j]) { bestS[j] = s; bestI[j] = v; }  // ascending v: first-min kept
            }
        }
    }
    // reduce across the 16 tv-lanes (segmented shuffle, width=16)
#pragma unroll
    for (int j = 0; j < 4; j++) {
#pragma unroll
        for (int off = 8; off; off >>= 1) {
            float os = __shfl_down_sync(0xffffffffu, bestS[j], off, 16);
            int   oi = __shfl_down_sync(0xffffffffu, bestI[j], off, 16);
            if (os < bestS[j] || (os == bestS[j] && oi < bestI[j])) {
                bestS[j] = os; bestI[j] = oi;
            }
        }
    }
    if (tv == 0) {
#pragma unroll
        for (int j = 0; j < 4; j++) {
            int pos = pt + tp * 4 + j;
            partS[seg * 8192 + pos] = bestS[j];
            partI[seg * 8192 + pos] = bestI[j];
        }
    }
}

// combine 4 segment-partials, emit tokens (int scratch + float to d_out)
__global__ void __launch_bounds__(256) vq_final(
    const float* __restrict__ partS, const int* __restrict__ partI,
    int* __restrict__ tok, float* __restrict__ outTok, int writeTok)
{
    int pos = blockIdx.x * blockDim.x + threadIdx.x;
    if (pos >= 8192) return;
    float bs = partS[pos];
    int   bi = partI[pos];
#pragma unroll
    for (int s = 1; s < 4; s++) {
        float v = partS[s * 8192 + pos];
        int   i = partI[s * 8192 + pos];
        if (v < bs || (v == bs && i < bi)) { bs = v; bi = i; }
    }
    tok[pos] = bi;
    if (writeTok) outTok[pos] = (float)bi;
}

// embeddings = emb_table[tokens]
__global__ void __launch_bounds__(256) gather_kernel(
    const int* __restrict__ tok, const float* __restrict__ emb,
    float* __restrict__ out)
{
    size_t idx = (size_t)blockIdx.x * blockDim.x + threadIdx.x; // 8192*128 float4s
    int pos = (int)(idx >> 7);
    int c4  = (int)(idx & 127);
    float4 v = *(const float4*)&emb[(size_t)tok[pos] * 512 + c4 * 4];
    *(float4*)&out[(size_t)pos * 512 + c4 * 4] = v;
}

// ---------------------------------------------------------------------------
// launch
// ---------------------------------------------------------------------------
extern "C" void kernel_launch(void* const* d_in, const int* in_sizes, int n_in,
                              void* d_out, int out_size)
{
    const float* video = (const float*)d_in[0];
    const float* w1    = (const float*)d_in[1];
    const float* b1    = (const float*)d_in[2];
    const float* w2    = (const float*)d_in[3];
    const float* b2    = (const float*)d_in[4];
    const float* w3    = (const float*)d_in[5];
    const float* b3    = (const float*)d_in[6];
    const float* cb    = (const float*)d_in[7];
    const float* emb   = (const float*)d_in[8];

    float *h1, *h2, *ff, *c2, *ps;
    int *pi, *tk;
    cudaGetSymbolAddress((void**)&h1, g_h1);
    cudaGetSymbolAddress((void**)&h2, g_h2);
    cudaGetSymbolAddress((void**)&ff, g_f);
    cudaGetSymbolAddress((void**)&c2, g_c2);
    cudaGetSymbolAddress((void**)&ps, g_ps);
    cudaGetSymbolAddress((void**)&pi, g_pi);
    cudaGetSymbolAddress((void**)&tk, g_tok);

    // conv1: [2,3,16,128,128] -> [2,128,16,64,64]
    conv3d_kernel<3, 128, 16, 128, 128, 64, 64, true>
        <<<dim3(131072 / 32, 2), 128>>>(video, w1, b1, h1);
    // conv2: -> [2,256,16,32,32]
    conv3d_kernel<128, 256, 16, 64, 64, 32, 32, true>
        <<<dim3(32768 / 32, 4), 128>>>(h1, w2, b2, h2);
    // conv3: -> [2,512,16,16,16]
    conv3d_kernel<256, 512, 16, 32, 32, 16, 16, false>
        <<<dim3(8192 / 32, 8), 128>>>(h2, w3, b3, ff);

    c2_kernel<<<1024, 256>>>(cb, c2);
    vq_kernel<<<dim3(256, 4), 128>>>(ff, cb, c2, ps, pi);

    float* outf = (float*)d_out;
    const int embElems = 8192 * 512;
    int writeTok = (out_size >= embElems + 8192) ? 1 : 0;
    float* embOut = outf + (writeTok ? 8192 : 0);

    vq_final<<<32, 256>>>(ps, pi, tk, outf, writeTok);
    gather_kernel<<<(8192 * 128) / 256, 256>>>(tk, emb, embOut);
}

// round 2
// speedup vs baseline: 1.9192x; 1.9192x over previous
#include <cuda_runtime.h>
#include <cstddef>

// ---------------------------------------------------------------------------
// VideoEncoder: 3x Conv3D (stride 1,2,2; pad 1) + VQ argmin + embedding gather
//   video [2,3,16,128,128] -> h1 [2,128,16,64,64] -> h2 [2,256,16,32,32]
//   -> f [2,512,16,16,16] -> tokens [2,4096] -> embeddings [2,4096,512]
// All GEMMs: 128x128 tile, 256 threads, 8x8 register blocking, reg-prefetch
// software pipeline. fp32 throughout; accumulation order matches round-1
// kernel bit-for-bit (k ascending, single accumulator).
// ---------------------------------------------------------------------------

__device__ float g_h1[2 * 128 * 16 * 64 * 64];   // 64 MB
__device__ float g_h2[2 * 256 * 16 * 32 * 32];   // 32 MB
__device__ float g_f [2 * 512 * 16 * 16 * 16];   // 16 MB
__device__ float g_c2[8192];
__device__ float g_ps[8 * 8192];
__device__ int   g_pi[8 * 8192];
__device__ int   g_tok[8192];

// ---------------------------------------------------------------------------
// conv3d as implicit-im2col GEMM, 128(co) x 128(pos) tile.
// ---------------------------------------------------------------------------
template<int CIN, int CO, int OT, int IH, int IW, int OH, int OW, bool RELU>
__global__ void __launch_bounds__(256, 2) conv3d_kernel(
    const float* __restrict__ x, const float* __restrict__ w,
    const float* __restrict__ bias, float* __restrict__ y)
{
    constexpr int K   = CIN * 27;
    constexpr int IT  = OT;
    constexpr int SPO = OT * OH * OW;
    constexpr int NCH = (K + 15) / 16;

    __shared__ float Ws[16][128];   // [k][co]
    __shared__ float Xs[16][128];   // [k][pos]

    const int tid = threadIdx.x;
    const int pt  = blockIdx.x * 128;
    const int cot = blockIdx.y * 128;
    const int b   = pt / SPO;          // 128 | SPO for all layers
    const int sp0 = pt - b * SPO;

    // X loader: thread stages k-row xk for 8 consecutive positions.
    // 8 consecutive flattened positions share (t,h) and have consecutive w
    // because pos offset and OW are both multiples of 8.
    const int xk = tid >> 4;           // 0..15
    const int xp = (tid & 15) * 8;
    const int spx = sp0 + xp;
    const int t0  = spx / (OH * OW);
    const int rhw = spx % (OH * OW);
    const int h0  = rhw / OW;
    const int w0  = rhw % OW;
    const float* xb = x + (size_t)b * CIN * (IT * IH * IW);

    // W loader: thread stages 8 consecutive k for one co row.
    const int wc = tid >> 1;           // 0..127
    const int wk = (tid & 1) * 8;
    const float* wrow = w + (size_t)(cot + wc) * K;

    // compute mapping: 16x16 thread grid, 8co x 8pos each
    const int tr = tid >> 4;
    const int tc = tid & 15;

    float wbuf[8], xbuf[8];
    float acc[8][8];
#pragma unroll
    for (int i = 0; i < 8; i++)
#pragma unroll
        for (int j = 0; j < 8; j++) acc[i][j] = 0.f;

    auto loadW = [&](int k0) {
        if constexpr (K % 16 == 0) {
            float4 v0 = *(const float4*)(wrow + k0 + wk);
            float4 v1 = *(const float4*)(wrow + k0 + wk + 4);
            wbuf[0] = v0.x; wbuf[1] = v0.y; wbuf[2] = v0.z; wbuf[3] = v0.w;
            wbuf[4] = v1.x; wbuf[5] = v1.y; wbuf[6] = v1.z; wbuf[7] = v1.w;
        } else {
#pragma unroll
            for (int q = 0; q < 8; q++) {
                int k = k0 + wk + q;
                wbuf[q] = (k < K) ? wrow[k] : 0.f;
            }
        }
    };
    auto loadX = [&](int k0) {
        int k = k0 + xk;
        if constexpr (K % 16 != 0) {
            if (k >= K) {
#pragma unroll
                for (int q = 0; q < 8; q++) xbuf[q] = 0.f;
                return;
            }
        }
        int ci = k / 27, tap = k - ci * 27;
        int kt = tap / 9, r9 = tap - kt * 9;
        int kh = r9 / 3,  kw = r9 - kh * 3;
        int it  = t0 + kt - 1;
        int ih  = 2 * h0 + kh - 1;
        int iw0 = 2 * w0 + kw - 1;
        bool okp = ((unsigned)it < (unsigned)IT) && ((unsigned)ih < (unsigned)IH);
        const float* px = xb + ((size_t)ci * IT + it) * (IH * IW) + (long)ih * IW;
#pragma unroll
        for (int q = 0; q < 8; q++) {
            int iw = iw0 + 2 * q;
            bool ok = okp && ((unsigned)iw < (unsigned)IW);
            xbuf[q] = ok ? px[iw] : 0.f;
        }
    };

    loadW(0);
    loadX(0);

    for (int c0 = 0; c0 < NCH; c0++) {
        __syncthreads();
#pragma unroll
        for (int q = 0; q < 8; q++) Ws[wk + q][wc] = wbuf[q];
        *(float4*)&Xs[xk][xp]     = *(float4*)&xbuf[0];
        *(float4*)&Xs[xk][xp + 4] = *(float4*)&xbuf[4];
        __syncthreads();
        if (c0 + 1 < NCH) { loadW((c0 + 1) * 16); loadX((c0 + 1) * 16); }

#pragma unroll
        for (int kk = 0; kk < 16; kk++) {
            float a[8], bx[8];
            *(float4*)&a[0]  = *(const float4*)&Ws[kk][tr * 8];
            *(float4*)&a[4]  = *(const float4*)&Ws[kk][tr * 8 + 4];
            *(float4*)&bx[0] = *(const float4*)&Xs[kk][tc * 8];
            *(float4*)&bx[4] = *(const float4*)&Xs[kk][tc * 8 + 4];
#pragma unroll
            for (int i = 0; i < 8; i++)
#pragma unroll
                for (int j = 0; j < 8; j++)
                    acc[i][j] = fmaf(a[i], bx[j], acc[i][j]);
        }
    }

    // epilogue: bias + relu + vectorized store
#pragma unroll
    for (int i = 0; i < 8; i++) {
        int co = cot + tr * 8 + i;
        float bv = bias[co];
        float o[8];
#pragma unroll
        for (int j = 0; j < 8; j++) {
            float v = acc[i][j] + bv;
            if (RELU) v = fmaxf(v, 0.f);
            o[j] = v;
        }
        float* yp = y + (size_t)(b * CO + co) * SPO + sp0 + tc * 8;
        *(float4*)yp       = *(float4*)&o[0];
        *(float4*)(yp + 4) = *(float4*)&o[4];
    }
}

// ---------------------------------------------------------------------------
// codebook row norms: one warp per row
// ---------------------------------------------------------------------------
__global__ void __launch_bounds__(256) c2_kernel(const float* __restrict__ cb,
                                                 float* __restrict__ c2)
{
    int v    = blockIdx.x * 8 + (threadIdx.x >> 5);
    int lane = threadIdx.x & 31;
    const float* r = cb + (size_t)v * 512;
    float s = 0.f;
#pragma unroll 4
    for (int c = lane; c < 512; c += 32) { float xv = r[c]; s = fmaf(xv, xv, s); }
#pragma unroll
    for (int off = 16; off; off >>= 1) s += __shfl_down_sync(0xffffffffu, s, off);
    if (lane == 0) c2[v] = s;
}

// ---------------------------------------------------------------------------
// VQ: 128(codes) x 128(pos) GEMM tiles; block scans a 1024-code segment
// (grid.y = 8 segments). s = ||c||^2 - 2*dot; argmin over codes.
// ---------------------------------------------------------------------------
__global__ void __launch_bounds__(256, 2) vq_kernel(
    const float* __restrict__ f, const float* __restrict__ cb,
    const float* __restrict__ c2, float* __restrict__ partS, int* __restrict__ partI)
{
    __shared__ float Cs[16][128];   // [k][v]
    __shared__ float Fs[16][128];   // [k][pos]
    __shared__ float redS[16][128];
    __shared__ int   redI[16][128];

    const int tid = threadIdx.x;
    const int tr  = tid >> 4;
    const int tc  = tid & 15;
    const int pt  = blockIdx.x * 128;   // 64 position tiles
    const int seg = blockIdx.y;         // 0..7
    const int b   = pt >> 12;
    const int sp0 = pt & 4095;

    const int fk = tid >> 4, fp = (tid & 15) * 8;
    const float* fbase = f + ((size_t)b * 512) * 4096 + sp0 + fp;
    const int wc = tid >> 1, wk = (tid & 1) * 8;

    float bestS[8];
    int   bestI[8];
#pragma unroll
    for (int j = 0; j < 8; j++) { bestS[j] = 3.4e38f; bestI[j] = 0; }

    float cbuf[8], fbuf[8];

    const int vend = seg * 1024 + 1024;
    for (int vt = seg * 1024; vt < vend; vt += 128) {
        const float* crow = cb + (size_t)(vt + wc) * 512;

        float acc[8][8];
#pragma unroll
        for (int i = 0; i < 8; i++)
#pragma unroll
            for (int j = 0; j < 8; j++) acc[i][j] = 0.f;

        // prefetch chunk 0
        {
            float4 v0 = *(const float4*)(crow + wk);
            float4 v1 = *(const float4*)(crow + wk + 4);
            cbuf[0]=v0.x; cbuf[1]=v0.y; cbuf[2]=v0.z; cbuf[3]=v0.w;
            cbuf[4]=v1.x; cbuf[5]=v1.y; cbuf[6]=v1.z; cbuf[7]=v1.w;
            const float* fr = fbase + (size_t)fk * 4096;
            float4 u0 = *(const float4*)fr;
            float4 u1 = *(const float4*)(fr + 4);
            fbuf[0]=u0.x; fbuf[1]=u0.y; fbuf[2]=u0.z; fbuf[3]=u0.w;
            fbuf[4]=u1.x; fbuf[5]=u1.y; fbuf[6]=u1.z; fbuf[7]=u1.w;
        }

        for (int c0 = 0; c0 < 32; c0++) {
            __syncthreads();
#pragma unroll
            for (int q = 0; q < 8; q++) Cs[wk + q][wc] = cbuf[q];
            *(float4*)&Fs[fk][fp]     = *(float4*)&fbuf[0];
            *(float4*)&Fs[fk][fp + 4] = *(float4*)&fbuf[4];
            __syncthreads();
            if (c0 + 1 < 32) {
                int k0 = (c0 + 1) * 16;
                float4 v0 = *(const float4*)(crow + k0 + wk);
                float4 v1 = *(const float4*)(crow + k0 + wk + 4);
                cbuf[0]=v0.x; cbuf[1]=v0.y; cbuf[2]=v0.z; cbuf[3]=v0.w;
                cbuf[4]=v1.x; cbuf[5]=v1.y; cbuf[6]=v1.z; cbuf[7]=v1.w;
                const float* fr = fbase + (size_t)(k0 + fk) * 4096;
                float4 u0 = *(const float4*)fr;
                float4 u1 = *(const float4*)(fr + 4);
                fbuf[0]=u0.x; fbuf[1]=u0.y; fbuf[2]=u0.z; fbuf[3]=u0.w;
                fbuf[4]=u1.x; fbuf[5]=u1.y; fbuf[6]=u1.z; fbuf[7]=u1.w;
            }
#pragma unroll
            for (int kk = 0; kk < 16; kk++) {
                float a[8], bx[8];
                *(float4*)&a[0]  = *(const float4*)&Cs[kk][tr * 8];
                *(float4*)&a[4]  = *(const float4*)&Cs[kk][tr * 8 + 4];
                *(float4*)&bx[0] = *(const float4*)&Fs[kk][tc * 8];
                *(float4*)&bx[4] = *(const float4*)&Fs[kk][tc * 8 + 4];
#pragma unroll
                for (int i = 0; i < 8; i++)
#pragma unroll
                    for (int j = 0; j < 8; j++)
                        acc[i][j] = fmaf(a[i], bx[j], acc[i][j]);
            }
        }

        // fold running min (v ascending; strict < keeps first min)
#pragma unroll
        for (int i = 0; i < 8; i++) {
            int v = vt + tr * 8 + i;
            float cc = __ldg(&c2[v]);
#pragma unroll
            for (int j = 0; j < 8; j++) {
                float s = fmaf(-2.f, acc[i][j], cc);
                if (s < bestS[j]) { bestS[j] = s; bestI[j] = v; }
            }
        }
    }

    // cross-thread reduce over the 16 code groups via smem
#pragma unroll
    for (int j = 0; j < 8; j++) {
        redS[tr][tc * 8 + j] = bestS[j];
        redI[tr][tc * 8 + j] = bestI[j];
    }
    __syncthreads();
    if (tid < 128) {
        float bs = redS[0][tid];
        int   bi = redI[0][tid];
#pragma unroll
        for (int r = 1; r < 16; r++) {
            float s = redS[r][tid];
            int   i = redI[r][tid];
            if (s < bs || (s == bs && i < bi)) { bs = s; bi = i; }
        }
        partS[seg * 8192 + pt + tid] = bs;
        partI[seg * 8192 + pt + tid] = bi;
    }
}

// combine 8 segment-partials, emit tokens
__global__ void __launch_bounds__(256) vq_final(
    const float* __restrict__ partS, const int* __restrict__ partI,
    int* __restrict__ tok, float* __restrict__ outTok, int writeTok)
{
    int pos = blockIdx.x * blockDim.x + threadIdx.x;
    if (pos >= 8192) return;
    float bs = partS[pos];
    int   bi = partI[pos];
#pragma unroll
    for (int s = 1; s < 8; s++) {
        float v = partS[s * 8192 + pos];
        int   i = partI[s * 8192 + pos];
        if (v < bs || (v == bs && i < bi)) { bs = v; bi = i; }
    }
    tok[pos] = bi;
    if (writeTok) outTok[pos] = (float)bi;
}

// embeddings = emb_table[tokens]
__global__ void __launch_bounds__(256) gather_kernel(
    const int* __restrict__ tok, const float* __restrict__ emb,
    float* __restrict__ out)
{
    size_t idx = (size_t)blockIdx.x * blockDim.x + threadIdx.x;
    int pos = (int)(idx >> 7);
    int c4  = (int)(idx & 127);
    float4 v = *(const float4*)&emb[(size_t)tok[pos] * 512 + c4 * 4];
    *(float4*)&out[(size_t)pos * 512 + c4 * 4] = v;
}

// ---------------------------------------------------------------------------
// launch
// ---------------------------------------------------------------------------
extern "C" void kernel_launch(void* const* d_in, const int* in_sizes, int n_in,
                              void* d_out, int out_size)
{
    const float* video = (const float*)d_in[0];
    const float* w1    = (const float*)d_in[1];
    const float* b1    = (const float*)d_in[2];
    const float* w2    = (const float*)d_in[3];
    const float* b2    = (const float*)d_in[4];
    const float* w3    = (const float*)d_in[5];
    const float* b3    = (const float*)d_in[6];
    const float* cb    = (const float*)d_in[7];
    const float* emb   = (const float*)d_in[8];

    float *h1, *h2, *ff, *c2, *ps;
    int *pi, *tk;
    cudaGetSymbolAddress((void**)&h1, g_h1);
    cudaGetSymbolAddress((void**)&h2, g_h2);
    cudaGetSymbolAddress((void**)&ff, g_f);
    cudaGetSymbolAddress((void**)&c2, g_c2);
    cudaGetSymbolAddress((void**)&ps, g_ps);
    cudaGetSymbolAddress((void**)&pi, g_pi);
    cudaGetSymbolAddress((void**)&tk, g_tok);

    // conv1: [2,3,16,128,128] -> [2,128,16,64,64]
    conv3d_kernel<3, 128, 16, 128, 128, 64, 64, true>
        <<<dim3(131072 / 128, 1), 256>>>(video, w1, b1, h1);
    // conv2: -> [2,256,16,32,32]
    conv3d_kernel<128, 256, 16, 64, 64, 32, 32, true>
        <<<dim3(32768 / 128, 2), 256>>>(h1, w2, b2, h2);
    // conv3: -> [2,512,16,16,16]
    conv3d_kernel<256, 512, 16, 32, 32, 16, 16, false>
        <<<dim3(8192 / 128, 4), 256>>>(h2, w3, b3, ff);

    c2_kernel<<<1024, 256>>>(cb, c2);
    vq_kernel<<<dim3(64, 8), 256>>>(ff, cb, c2, ps, pi);

    float* outf = (float*)d_out;
    const int embElems = 8192 * 512;
    int writeTok = (out_size >= embElems + 8192) ? 1 : 0;
    float* embOut = outf + (writeTok ? 8192 : 0);

    vq_final<<<32, 256>>>(ps, pi, tk, outf, writeTok);
    gather_kernel<<<(8192 * 128) / 256, 256>>>(tk, emb, embOut);
}

// round 4
// speedup vs baseline: 2.0939x; 1.0910x over previous
#include <cuda_runtime.h>
#include <cstdint>
#include <cstddef>

// ---------------------------------------------------------------------------
// VideoEncoder: 3x Conv3D (stride 1,2,2; pad 1) + VQ argmin + embedding gather
// R4: VQ via warp-level mma.sync tf32 (3-MMA hi/lo split) — portable PTX
//     (tcgen05 is rejected by the harness's non-'a' PTX target).
// Convs remain the scalar 128x128 GEMM (R2).
// ---------------------------------------------------------------------------

__device__ float g_h1[2 * 128 * 16 * 64 * 64];   // 64 MB
__device__ float g_h2[2 * 256 * 16 * 32 * 32];   // 32 MB
__device__ float g_f [2 * 512 * 16 * 16 * 16];   // 16 MB
__device__ float g_cbT[512 * 8192];              // 16 MB codebook^T [c][v]
__device__ float g_c2[8192];
__device__ float g_ps[8 * 8192];
__device__ int   g_pi[8 * 8192];
__device__ int   g_tok[8192];

// ---------------------------------------------------------------------------
// helpers
// ---------------------------------------------------------------------------
__device__ __forceinline__ uint32_t smem_u32(const void* p) {
    uint32_t a;
    asm("{ .reg .u64 t; cvta.to.shared.u64 t, %1; cvt.u32.u64 %0, t; }"
        : "=r"(a) : "l"(p));
    return a;
}
__device__ __forceinline__ void cp16(uint32_t s, const void* g) {
    asm volatile("cp.async.cg.shared.global [%0], [%1], 16;" :: "r"(s), "l"(g));
}
__device__ __forceinline__ void cpcommit() {
    asm volatile("cp.async.commit_group;" ::: "memory");
}
template<int N> __device__ __forceinline__ void cpwait() {
    asm volatile("cp.async.wait_group %0;" :: "n"(N) : "memory");
}
// fp32 -> tf32 hi + lo (bit patterns for mma operands)
__device__ __forceinline__ void split1(float x, uint32_t& h, uint32_t& l) {
    asm("cvt.rna.tf32.f32 %0, %1;" : "=r"(h) : "f"(x));
    float r = x - __uint_as_float(h);
    asm("cvt.rna.tf32.f32 %0, %1;" : "=r"(l) : "f"(r));
}
__device__ __forceinline__ void mma8(float* c, const uint32_t* a, const uint32_t* b) {
    asm volatile("mma.sync.aligned.m16n8k8.row.col.f32.tf32.tf32.f32 "
        "{%0,%1,%2,%3}, {%4,%5,%6,%7}, {%8,%9}, {%0,%1,%2,%3};"
        : "+f"(c[0]), "+f"(c[1]), "+f"(c[2]), "+f"(c[3])
        : "r"(a[0]), "r"(a[1]), "r"(a[2]), "r"(a[3]), "r"(b[0]), "r"(b[1]));
}

// ---------------------------------------------------------------------------
// conv3d (scalar GEMM, unchanged from R2)
// ---------------------------------------------------------------------------
template<int CIN, int CO, int OT, int IH, int IW, int OH, int OW, bool RELU>
__global__ void __launch_bounds__(256, 2) conv3d_kernel(
    const float* __restrict__ x, const float* __restrict__ w,
    const float* __restrict__ bias, float* __restrict__ y)
{
    constexpr int K   = CIN * 27;
    constexpr int IT  = OT;
    constexpr int SPO = OT * OH * OW;
    constexpr int NCH = (K + 15) / 16;

    __shared__ float Ws[16][128];
    __shared__ float Xs[16][128];

    const int tid = threadIdx.x;
    const int pt  = blockIdx.x * 128;
    const int cot = blockIdx.y * 128;
    const int b   = pt / SPO;
    const int sp0 = pt - b * SPO;

    const int xk = tid >> 4;
    const int xp = (tid & 15) * 8;
    const int spx = sp0 + xp;
    const int t0  = spx / (OH * OW);
    const int rhw = spx % (OH * OW);
    const int h0  = rhw / OW;
    const int w0  = rhw % OW;
    const float* xb = x + (size_t)b * CIN * (IT * IH * IW);

    const int wc = tid >> 1;
    const int wk = (tid & 1) * 8;
    const float* wrow = w + (size_t)(cot + wc) * K;

    const int tr = tid >> 4;
    const int tc = tid & 15;

    float wbuf[8], xbuf[8];
    float acc[8][8];
#pragma unroll
    for (int i = 0; i < 8; i++)
#pragma unroll
        for (int j = 0; j < 8; j++) acc[i][j] = 0.f;

    auto loadW = [&](int k0) {
        if constexpr (K % 16 == 0) {
            float4 v0 = *(const float4*)(wrow + k0 + wk);
            float4 v1 = *(const float4*)(wrow + k0 + wk + 4);
            wbuf[0] = v0.x; wbuf[1] = v0.y; wbuf[2] = v0.z; wbuf[3] = v0.w;
            wbuf[4] = v1.x; wbuf[5] = v1.y; wbuf[6] = v1.z; wbuf[7] = v1.w;
        } else {
#pragma unroll
            for (int q = 0; q < 8; q++) {
                int k = k0 + wk + q;
                wbuf[q] = (k < K) ? wrow[k] : 0.f;
            }
        }
    };
    auto loadX = [&](int k0) {
        int k = k0 + xk;
        if constexpr (K % 16 != 0) {
            if (k >= K) {
#pragma unroll
                for (int q = 0; q < 8; q++) xbuf[q] = 0.f;
                return;
            }
        }
        int ci = k / 27, tap = k - ci * 27;
        int kt = tap / 9, r9 = tap - kt * 9;
        int kh = r9 / 3,  kw = r9 - kh * 3;
        int it  = t0 + kt - 1;
        int ih  = 2 * h0 + kh - 1;
        int iw0 = 2 * w0 + kw - 1;
        bool okp = ((unsigned)it < (unsigned)IT) && ((unsigned)ih < (unsigned)IH);
        const float* px = xb + ((size_t)ci * IT + it) * (IH * IW) + (long)ih * IW;
#pragma unroll
        for (int q = 0; q < 8; q++) {
            int iw = iw0 + 2 * q;
            bool ok = okp && ((unsigned)iw < (unsigned)IW);
            xbuf[q] = ok ? px[iw] : 0.f;
        }
    };

    loadW(0);
    loadX(0);

    for (int c0 = 0; c0 < NCH; c0++) {
        __syncthreads();
#pragma unroll
        for (int q = 0; q < 8; q++) Ws[wk + q][wc] = wbuf[q];
        *(float4*)&Xs[xk][xp]     = *(float4*)&xbuf[0];
        *(float4*)&Xs[xk][xp + 4] = *(float4*)&xbuf[4];
        __syncthreads();
        if (c0 + 1 < NCH) { loadW((c0 + 1) * 16); loadX((c0 + 1) * 16); }

#pragma unroll
        for (int kk = 0; kk < 16; kk++) {
            float a[8], bx[8];
            *(float4*)&a[0]  = *(const float4*)&Ws[kk][tr * 8];
            *(float4*)&a[4]  = *(const float4*)&Ws[kk][tr * 8 + 4];
            *(float4*)&bx[0] = *(const float4*)&Xs[kk][tc * 8];
            *(float4*)&bx[4] = *(const float4*)&Xs[kk][tc * 8 + 4];
#pragma unroll
            for (int i = 0; i < 8; i++)
#pragma unroll
                for (int j = 0; j < 8; j++)
                    acc[i][j] = fmaf(a[i], bx[j], acc[i][j]);
        }
    }

#pragma unroll
    for (int i = 0; i < 8; i++) {
        int co = cot + tr * 8 + i;
        float bv = bias[co];
        float o[8];
#pragma unroll
        for (int j = 0; j < 8; j++) {
            float v = acc[i][j] + bv;
            if (RELU) v = fmaxf(v, 0.f);
            o[j] = v;
        }
        float* yp = y + (size_t)(b * CO + co) * SPO + sp0 + tc * 8;
        *(float4*)yp       = *(float4*)&o[0];
        *(float4*)(yp + 4) = *(float4*)&o[4];
    }
}

// ---------------------------------------------------------------------------
// codebook transpose [8192][512] -> [512][8192]
// ---------------------------------------------------------------------------
__global__ void __launch_bounds__(256) transpose_cb(
    const float* __restrict__ cb, float* __restrict__ cbT)
{
    __shared__ float t[32][33];
    const int tx = threadIdx.x & 31, ty = threadIdx.x >> 5;
    const int v0 = blockIdx.x * 32, c0 = blockIdx.y * 32;
#pragma unroll
    for (int i = 0; i < 4; i++)
        t[ty + i * 8][tx] = cb[(size_t)(v0 + ty + i * 8) * 512 + c0 + tx];
    __syncthreads();
#pragma unroll
    for (int i = 0; i < 4; i++)
        cbT[(size_t)(c0 + ty + i * 8) * 8192 + v0 + tx] = t[tx][ty + i * 8];
}

// codebook row norms
__global__ void __launch_bounds__(256) c2_kernel(const float* __restrict__ cb,
                                                 float* __restrict__ c2)
{
    int v    = blockIdx.x * 8 + (threadIdx.x >> 5);
    int lane = threadIdx.x & 31;
    const float* r = cb + (size_t)v * 512;
    float s = 0.f;
#pragma unroll 4
    for (int c = lane; c < 512; c += 32) { float xv = r[c]; s = fmaf(xv, xv, s); }
#pragma unroll
    for (int off = 16; off; off >>= 1) s += __shfl_down_sync(0xffffffffu, s, off);
    if (lane == 0) c2[v] = s;
}

// ---------------------------------------------------------------------------
// VQ via mma.sync tf32: block = 128 pos x 128 codes, 8 warps (2x4),
// warp tile 64x32 = 4x4 m16n8k8 sites, 3-MMA hi/lo split.
// grid (64 pos-tiles, 8 segments of 1024 codes).
// ---------------------------------------------------------------------------
struct VqSmem {
    union {
        struct { float As[2][16][136]; float Bs[2][16][136]; } gm;
        struct { float S[128][17]; int I[128][17]; } red;
    };
};

__global__ void __launch_bounds__(256, 1) vq_mma_kernel(
    const float* __restrict__ f,      // [2][512][4096]
    const float* __restrict__ cbT,    // [512][8192]
    const float* __restrict__ c2,
    float* __restrict__ partS, int* __restrict__ partI)
{
    __shared__ VqSmem sm;

    const int tid  = threadIdx.x;
    const int wid  = tid >> 5;
    const int lane = tid & 31;
    const int lr   = lane >> 2, lc = lane & 3;
    const int mw   = wid >> 2,  nw = wid & 3;
    const int m0   = mw * 64,   n0 = nw * 32;

    const int pt  = blockIdx.x * 128;
    const int seg = blockIdx.y;
    const int b   = pt >> 12;
    const int sp0 = pt & 4095;
    const float* fb = f + (size_t)b * 512 * 4096;

    // loader slots: 2 x (row, quad)
    const int r0l = tid >> 5;            // wait: see below (recomputed per i)

    float bS[8];
    int   bI[8];
#pragma unroll
    for (int i = 0; i < 8; i++) { bS[i] = 3.4e38f; bI[i] = 0; }

    for (int nt = 0; nt < 8; nt++) {
        const int vt = seg * 1024 + nt * 128;

        float acc[4][4][4];
#pragma unroll
        for (int a = 0; a < 4; a++)
#pragma unroll
            for (int c = 0; c < 4; c++)
#pragma unroll
                for (int r = 0; r < 4; r++) acc[a][c][r] = 0.f;

        auto issue = [&](int ch, int s) {
            const int k0g = ch * 16;
#pragma unroll
            for (int i = 0; i < 2; i++) {
                int idx = tid + i * 256;
                int r = idx >> 5, q = idx & 31;
                cp16(smem_u32(&sm.gm.As[s][r][4 * q]),
                     fb + (size_t)(k0g + r) * 4096 + sp0 + 4 * q);
                cp16(smem_u32(&sm.gm.Bs[s][r][4 * q]),
                     cbT + (size_t)(k0g + r) * 8192 + vt + 4 * q);
            }
            cpcommit();
        };

        issue(0, 0);
        int s = 0;
        for (int ch = 0; ch < 32; ch++) {
            if (ch + 1 < 32) { issue(ch + 1, s ^ 1); cpwait<1>(); }
            else             { cpwait<0>(); }
            __syncthreads();

#pragma unroll
            for (int ks = 0; ks < 2; ks++) {
                const int k = ks * 8;
                uint32_t ah[4][4], al[4][4];
#pragma unroll
                for (int mf = 0; mf < 4; mf++) {
                    int rr = m0 + mf * 16 + lr;
                    split1(sm.gm.As[s][k + lc][rr],          ah[mf][0], al[mf][0]);
                    split1(sm.gm.As[s][k + lc][rr + 8],      ah[mf][1], al[mf][1]);
                    split1(sm.gm.As[s][k + lc + 4][rr],      ah[mf][2], al[mf][2]);
                    split1(sm.gm.As[s][k + lc + 4][rr + 8],  ah[mf][3], al[mf][3]);
                }
                uint32_t bh[4][2], bl[4][2];
#pragma unroll
                for (int nf = 0; nf < 4; nf++) {
                    int nn = n0 + nf * 8 + lr;
                    split1(sm.gm.Bs[s][k + lc][nn],     bh[nf][0], bl[nf][0]);
                    split1(sm.gm.Bs[s][k + lc + 4][nn], bh[nf][1], bl[nf][1]);
                }
#pragma unroll
                for (int mf = 0; mf < 4; mf++)
#pragma unroll
                    for (int nf = 0; nf < 4; nf++) {
                        mma8(acc[mf][nf], ah[mf], bh[nf]);
                        mma8(acc[mf][nf], ah[mf], bl[nf]);
                        mma8(acc[mf][nf], al[mf], bh[nf]);
                    }
            }
            __syncthreads();
            s ^= 1;
        }

        // fold distances into per-thread best (cols ascending within thread)
#pragma unroll
        for (int mf = 0; mf < 4; mf++)
#pragma unroll
            for (int half = 0; half < 2; half++) {
                int bslot = mf * 2 + half;
                float bs = bS[bslot];
                int   bi = bI[bslot];
#pragma unroll
                for (int nf = 0; nf < 4; nf++)
#pragma unroll
                    for (int r = 0; r < 2; r++) {
                        int col = vt + n0 + nf * 8 + 2 * lc + r;
                        float d = fmaf(-2.f, acc[mf][nf][half * 2 + r],
                                       __ldg(&c2[col]));
                        if (d < bs) { bs = d; bi = col; }
                    }
                bS[bslot] = bs;
                bI[bslot] = bi;
            }
    }

    // reduction: 16 contributors per row (4 lanes x 4 n-warps)
    __syncthreads();   // done with gm union before red reuse
#pragma unroll
    for (int mf = 0; mf < 4; mf++)
#pragma unroll
        for (int half = 0; half < 2; half++) {
            int rowl = m0 + mf * 16 + half * 8 + lr;
            int slot = nw * 4 + lc;
            sm.red.S[rowl][slot] = bS[mf * 2 + half];
            sm.red.I[rowl][slot] = bI[mf * 2 + half];
        }
    __syncthreads();
    if (tid < 128) {
        float bs = sm.red.S[tid][0];
        int   bi = sm.red.I[tid][0];
#pragma unroll
        for (int q = 1; q < 16; q++) {
            float v = sm.red.S[tid][q];
            int   i = sm.red.I[tid][q];
            if (v < bs || (v == bs && i < bi)) { bs = v; bi = i; }
        }
        partS[seg * 8192 + pt + tid] = bs;
        partI[seg * 8192 + pt + tid] = bi;
    }
}

// ---------------------------------------------------------------------------
// combine 8 segment partials + tokens; embedding gather
// ---------------------------------------------------------------------------
__global__ void __launch_bounds__(256) vq_final(
    const float* __restrict__ partS, const int* __restrict__ partI,
    int* __restrict__ tok, float* __restrict__ outTok, int writeTok)
{
    int pos = blockIdx.x * blockDim.x + threadIdx.x;
    if (pos >= 8192) return;
    float bs = partS[pos];
    int   bi = partI[pos];
#pragma unroll
    for (int s = 1; s < 8; s++) {
        float v = partS[s * 8192 + pos];
        int   i = partI[s * 8192 + pos];
        if (v < bs || (v == bs && i < bi)) { bs = v; bi = i; }
    }
    tok[pos] = bi;
    if (writeTok) outTok[pos] = (float)bi;
}

__global__ void __launch_bounds__(256) gather_kernel(
    const int* __restrict__ tok, const float* __restrict__ emb,
    float* __restrict__ out)
{
    size_t idx = (size_t)blockIdx.x * blockDim.x + threadIdx.x;
    int pos = (int)(idx >> 7);
    int c4  = (int)(idx & 127);
    float4 v = *(const float4*)&emb[(size_t)tok[pos] * 512 + c4 * 4];
    *(float4*)&out[(size_t)pos * 512 + c4 * 4] = v;
}

// ---------------------------------------------------------------------------
// launch
// ---------------------------------------------------------------------------
extern "C" void kernel_launch(void* const* d_in, const int* in_sizes, int n_in,
                              void* d_out, int out_size)
{
    const float* video = (const float*)d_in[0];
    const float* w1    = (const float*)d_in[1];
    const float* b1    = (const float*)d_in[2];
    const float* w2    = (const float*)d_in[3];
    const float* b2    = (const float*)d_in[4];
    const float* w3    = (const float*)d_in[5];
    const float* b3    = (const float*)d_in[6];
    const float* cb    = (const float*)d_in[7];
    const float* emb   = (const float*)d_in[8];

    float *h1, *h2, *ff, *cbT, *c2, *ps;
    int *pi, *tk;
    cudaGetSymbolAddress((void**)&h1, g_h1);
    cudaGetSymbolAddress((void**)&h2, g_h2);
    cudaGetSymbolAddress((void**)&ff, g_f);
    cudaGetSymbolAddress((void**)&cbT, g_cbT);
    cudaGetSymbolAddress((void**)&c2, g_c2);
    cudaGetSymbolAddress((void**)&ps, g_ps);
    cudaGetSymbolAddress((void**)&pi, g_pi);
    cudaGetSymbolAddress((void**)&tk, g_tok);

    conv3d_kernel<3, 128, 16, 128, 128, 64, 64, true>
        <<<dim3(131072 / 128, 1), 256>>>(video, w1, b1, h1);
    conv3d_kernel<128, 256, 16, 64, 64, 32, 32, true>
        <<<dim3(32768 / 128, 2), 256>>>(h1, w2, b2, h2);
    conv3d_kernel<256, 512, 16, 32, 32, 16, 16, false>
        <<<dim3(8192 / 128, 4), 256>>>(h2, w3, b3, ff);

    transpose_cb<<<dim3(256, 16), 256>>>(cb, cbT);
    c2_kernel<<<1024, 256>>>(cb, c2);

    vq_mma_kernel<<<dim3(64, 8), 256>>>(ff, cbT, c2, ps, pi);

    float* outf = (float*)d_out;
    const int embElems = 8192 * 512;
    int writeTok = (out_size >= embElems + 8192) ? 1 : 0;
    float* embOut = outf + (writeTok ? 8192 : 0);

    vq_final<<<32, 256>>>(ps, pi, tk, outf, writeTok);
    gather_kernel<<<(8192 * 128) / 256, 256>>>(tk, emb, embOut);
}

// round 5
// speedup vs baseline: 2.2161x; 1.0584x over previous
#include <cuda_runtime.h>
#include <cstdint>
#include <cstddef>

// ---------------------------------------------------------------------------
// VideoEncoder: 3x Conv3D (stride 1,2,2; pad 1) + VQ argmin + embedding gather
// R5: VQ mainloop = pure LDS + mma.sync tf32 (hi/lo pre-split into
//     fragment-major global arrays; no cvt / scalar gathers in the loop).
// Convs remain the scalar 128x128 GEMM (R2).
// ---------------------------------------------------------------------------

__device__ float g_h1[2 * 128 * 16 * 64 * 64];   // 64 MB
__device__ float g_h2[2 * 256 * 16 * 32 * 32];   // 32 MB
__device__ float g_f [2 * 512 * 16 * 16 * 16];   // 16 MB
// fragment-major split arrays
__device__ float g_Afh[512 * 64 * 32 * 4];       // 16 MB  f  hi  [mt][kt][lane][4]
__device__ float g_Afl[512 * 64 * 32 * 4];       // 16 MB  f  lo
__device__ float g_Bfh[1024 * 64 * 32 * 2];      // 16 MB  cb hi  [nt][kt][lane][2]
__device__ float g_Bfl[1024 * 64 * 32 * 2];      // 16 MB  cb lo
__device__ float g_c2[8192];
__device__ float g_ps[8 * 8192];
__device__ int   g_pi[8 * 8192];
__device__ int   g_tok[8192];

// ---------------------------------------------------------------------------
// helpers
// ---------------------------------------------------------------------------
__device__ __forceinline__ uint32_t smem_u32(const void* p) {
    uint32_t a;
    asm("{ .reg .u64 t; cvta.to.shared.u64 t, %1; cvt.u32.u64 %0, t; }"
        : "=r"(a) : "l"(p));
    return a;
}
__device__ __forceinline__ void cp16(uint32_t s, const void* g) {
    asm volatile("cp.async.cg.shared.global [%0], [%1], 16;" :: "r"(s), "l"(g));
}
__device__ __forceinline__ void cpcommit() {
    asm volatile("cp.async.commit_group;" ::: "memory");
}
template<int N> __device__ __forceinline__ void cpwait() {
    asm volatile("cp.async.wait_group %0;" :: "n"(N) : "memory");
}
__device__ __forceinline__ void split1(float x, float& h, float& l) {
    uint32_t hb, lb;
    asm("cvt.rna.tf32.f32 %0, %1;" : "=r"(hb) : "f"(x));
    float r = x - __uint_as_float(hb);
    asm("cvt.rna.tf32.f32 %0, %1;" : "=r"(lb) : "f"(r));
    h = __uint_as_float(hb);
    l = __uint_as_float(lb);
}
__device__ __forceinline__ void mma8(float* c, const uint32_t* a, const uint32_t* b) {
    asm volatile("mma.sync.aligned.m16n8k8.row.col.f32.tf32.tf32.f32 "
        "{%0,%1,%2,%3}, {%4,%5,%6,%7}, {%8,%9}, {%0,%1,%2,%3};"
        : "+f"(c[0]), "+f"(c[1]), "+f"(c[2]), "+f"(c[3])
        : "r"(a[0]), "r"(a[1]), "r"(a[2]), "r"(a[3]), "r"(b[0]), "r"(b[1]));
}

// ---------------------------------------------------------------------------
// conv3d (scalar GEMM, unchanged from R2)
// ---------------------------------------------------------------------------
template<int CIN, int CO, int OT, int IH, int IW, int OH, int OW, bool RELU>
__global__ void __launch_bounds__(256, 2) conv3d_kernel(
    const float* __restrict__ x, const float* __restrict__ w,
    const float* __restrict__ bias, float* __restrict__ y)
{
    constexpr int K   = CIN * 27;
    constexpr int IT  = OT;
    constexpr int SPO = OT * OH * OW;
    constexpr int NCH = (K + 15) / 16;

    __shared__ float Ws[16][128];
    __shared__ float Xs[16][128];

    const int tid = threadIdx.x;
    const int pt  = blockIdx.x * 128;
    const int cot = blockIdx.y * 128;
    const int b   = pt / SPO;
    const int sp0 = pt - b * SPO;

    const int xk = tid >> 4;
    const int xp = (tid & 15) * 8;
    const int spx = sp0 + xp;
    const int t0  = spx / (OH * OW);
    const int rhw = spx % (OH * OW);
    const int h0  = rhw / OW;
    const int w0  = rhw % OW;
    const float* xb = x + (size_t)b * CIN * (IT * IH * IW);

    const int wc = tid >> 1;
    const int wk = (tid & 1) * 8;
    const float* wrow = w + (size_t)(cot + wc) * K;

    const int tr = tid >> 4;
    const int tc = tid & 15;

    float wbuf[8], xbuf[8];
    float acc[8][8];
#pragma unroll
    for (int i = 0; i < 8; i++)
#pragma unroll
        for (int j = 0; j < 8; j++) acc[i][j] = 0.f;

    auto loadW = [&](int k0) {
        if constexpr (K % 16 == 0) {
            float4 v0 = *(const float4*)(wrow + k0 + wk);
            float4 v1 = *(const float4*)(wrow + k0 + wk + 4);
            wbuf[0] = v0.x; wbuf[1] = v0.y; wbuf[2] = v0.z; wbuf[3] = v0.w;
            wbuf[4] = v1.x; wbuf[5] = v1.y; wbuf[6] = v1.z; wbuf[7] = v1.w;
        } else {
#pragma unroll
            for (int q = 0; q < 8; q++) {
                int k = k0 + wk + q;
                wbuf[q] = (k < K) ? wrow[k] : 0.f;
            }
        }
    };
    auto loadX = [&](int k0) {
        int k = k0 + xk;
        if constexpr (K % 16 != 0) {
            if (k >= K) {
#pragma unroll
                for (int q = 0; q < 8; q++) xbuf[q] = 0.f;
                return;
            }
        }
        int ci = k / 27, tap = k - ci * 27;
        int kt = tap / 9, r9 = tap - kt * 9;
        int kh = r9 / 3,  kw = r9 - kh * 3;
        int it  = t0 + kt - 1;
        int ih  = 2 * h0 + kh - 1;
        int iw0 = 2 * w0 + kw - 1;
        bool okp = ((unsigned)it < (unsigned)IT) && ((unsigned)ih < (unsigned)IH);
        const float* px = xb + ((size_t)ci * IT + it) * (IH * IW) + (long)ih * IW;
#pragma unroll
        for (int q = 0; q < 8; q++) {
            int iw = iw0 + 2 * q;
            bool ok = okp && ((unsigned)iw < (unsigned)IW);
            xbuf[q] = ok ? px[iw] : 0.f;
        }
    };

    loadW(0);
    loadX(0);

    for (int c0 = 0; c0 < NCH; c0++) {
        __syncthreads();
#pragma unroll
        for (int q = 0; q < 8; q++) Ws[wk + q][wc] = wbuf[q];
        *(float4*)&Xs[xk][xp]     = *(float4*)&xbuf[0];
        *(float4*)&Xs[xk][xp + 4] = *(float4*)&xbuf[4];
        __syncthreads();
        if (c0 + 1 < NCH) { loadW((c0 + 1) * 16); loadX((c0 + 1) * 16); }

#pragma unroll
        for (int kk = 0; kk < 16; kk++) {
            float a[8], bx[8];
            *(float4*)&a[0]  = *(const float4*)&Ws[kk][tr * 8];
            *(float4*)&a[4]  = *(const float4*)&Ws[kk][tr * 8 + 4];
            *(float4*)&bx[0] = *(const float4*)&Xs[kk][tc * 8];
            *(float4*)&bx[4] = *(const float4*)&Xs[kk][tc * 8 + 4];
#pragma unroll
            for (int i = 0; i < 8; i++)
#pragma unroll
                for (int j = 0; j < 8; j++)
                    acc[i][j] = fmaf(a[i], bx[j], acc[i][j]);
        }
    }

#pragma unroll
    for (int i = 0; i < 8; i++) {
        int co = cot + tr * 8 + i;
        float bv = bias[co];
        float o[8];
#pragma unroll
        for (int j = 0; j < 8; j++) {
            float v = acc[i][j] + bv;
            if (RELU) v = fmaxf(v, 0.f);
            o[j] = v;
        }
        float* yp = y + (size_t)(b * CO + co) * SPO + sp0 + tc * 8;
        *(float4*)yp       = *(float4*)&o[0];
        *(float4*)(yp + 4) = *(float4*)&o[4];
    }
}

// ---------------------------------------------------------------------------
// codebook -> fragment-major hi/lo split
//   Bf[(nt*64 + kt)*32 + lane][2] : b0 = cb[nt*8+lr][kt*8+lc], b1 = [.. lc+4]
// ---------------------------------------------------------------------------
__global__ void __launch_bounds__(256) split_cb_kernel(
    const float* __restrict__ cb, float* __restrict__ Bfh, float* __restrict__ Bfl)
{
    const int wid  = threadIdx.x >> 5;
    const int lane = threadIdx.x & 31;
    const int lr = lane >> 2, lc = lane & 3;
    const int nt = blockIdx.x * 4 + (wid & 3);
    const int v  = nt * 8 + lr;
    const float* row = cb + (size_t)v * 512;
    for (int i = 0; i < 32; i++) {
        int kt = (wid >> 2) + 2 * i;
        float x0 = row[kt * 8 + lc];
        float x1 = row[kt * 8 + lc + 4];
        float h0, l0, h1, l1;
        split1(x0, h0, l0);
        split1(x1, h1, l1);
        size_t idx = ((size_t)(nt * 64 + kt) * 32 + lane) * 2;
        *(float2*)(Bfh + idx) = make_float2(h0, h1);
        *(float2*)(Bfl + idx) = make_float2(l0, l1);
    }
}

// codebook row norms (deterministic warp reduce)
__global__ void __launch_bounds__(256) c2_kernel(const float* __restrict__ cb,
                                                 float* __restrict__ c2)
{
    int v    = blockIdx.x * 8 + (threadIdx.x >> 5);
    int lane = threadIdx.x & 31;
    const float* r = cb + (size_t)v * 512;
    float s = 0.f;
#pragma unroll 4
    for (int c = lane; c < 512; c += 32) { float xv = r[c]; s = fmaf(xv, xv, s); }
#pragma unroll
    for (int off = 16; off; off >>= 1) s += __shfl_down_sync(0xffffffffu, s, off);
    if (lane == 0) c2[v] = s;
}

// ---------------------------------------------------------------------------
// f [2][512][4096] -> fragment-major hi/lo split over positions
//   Af[(mt*64+kt)*32+lane][4] : a0=fT[mt*16+lr][kt*8+lc] a1=row+8 a2=k+4 a3=both
// ---------------------------------------------------------------------------
__global__ void __launch_bounds__(256) split_f_kernel(
    const float* __restrict__ f, float* __restrict__ Afh, float* __restrict__ Afl)
{
    const int mt = blockIdx.x;              // 0..511
    const int p0 = mt * 16;
    const int b  = p0 >> 12;
    const int sp0 = p0 & 4095;
    const float* fb = f + (size_t)b * 512 * 4096;
#pragma unroll
    for (int i = 0; i < 8; i++) {
        int slot = threadIdx.x + i * 256;   // 2048 slots
        int kt = slot >> 5, lane = slot & 31;
        int lr = lane >> 2, lc = lane & 3;
        int k0 = kt * 8 + lc;
        float a0 = fb[(size_t)k0 * 4096 + sp0 + lr];
        float a1 = fb[(size_t)k0 * 4096 + sp0 + lr + 8];
        float a2 = fb[(size_t)(k0 + 4) * 4096 + sp0 + lr];
        float a3 = fb[(size_t)(k0 + 4) * 4096 + sp0 + lr + 8];
        float h0, l0, h1, l1, h2, l2, h3, l3;
        split1(a0, h0, l0); split1(a1, h1, l1);
        split1(a2, h2, l2); split1(a3, h3, l3);
        size_t idx = ((size_t)(mt * 64 + kt) * 32 + lane) * 4;
        *(float4*)(Afh + idx) = make_float4(h0, h1, h2, h3);
        *(float4*)(Afl + idx) = make_float4(l0, l1, l2, l3);
    }
}

// ---------------------------------------------------------------------------
// VQ: 128 pos x 128 codes per CTA-tile, pure LDS+mma mainloop.
// grid (64 pos-tiles, 8 segments of 1024 codes), 256 threads (8 warps, 2x4).
// Dynamic smem: 2 stages x (A 16KB + B 16KB) = 64 KB.
//   stage float layout: A [hl][mtl(8)][ktl(2)][128], B at +4096 [hl][ntl(16)][ktl(2)][64]
// ---------------------------------------------------------------------------
static constexpr int VQ_SMEM = 2 * 8192 * 4;   // 65536 B

__global__ void __launch_bounds__(256) vq_frag_kernel(
    const float* __restrict__ Afh, const float* __restrict__ Afl,
    const float* __restrict__ Bfh, const float* __restrict__ Bfl,
    const float* __restrict__ c2,
    float* __restrict__ partS, int* __restrict__ partI)
{
    extern __shared__ float sm[];

    const int tid  = threadIdx.x;
    const int wid  = tid >> 5;
    const int lane = tid & 31;
    const int lr   = lane >> 2, lc = lane & 3;
    const int mw   = wid >> 2,  nw = wid & 3;

    const int pt  = blockIdx.x * 128;
    const int seg = blockIdx.y;
    const int mt0 = blockIdx.x * 8;

    float bS[8];
    int   bI[8];
#pragma unroll
    for (int i = 0; i < 8; i++) { bS[i] = 3.4e38f; bI[i] = 0; }

    for (int tile = 0; tile < 8; tile++) {
        const int nt0 = seg * 128 + tile * 16;
        const int vt  = seg * 1024 + tile * 128;

        float acc[4][4][4];
#pragma unroll
        for (int a = 0; a < 4; a++)
#pragma unroll
            for (int c = 0; c < 4; c++)
#pragma unroll
                for (int r = 0; r < 4; r++) acc[a][c][r] = 0.f;

        auto issue = [&](int ch, int s) {
            float* st = sm + s * 8192;
            const int kt0 = ch * 2;
#pragma unroll
            for (int i = 0; i < 4; i++) {
                int slot = tid + i * 256;
                int hl = slot >> 9, mtl = (slot >> 6) & 7;
                int ktl = (slot >> 5) & 1, ln = slot & 31;
                const float* src = (hl ? Afl : Afh)
                    + ((size_t)((mt0 + mtl) * 64 + kt0 + ktl) * 32 + ln) * 4;
                cp16(smem_u32(st + ((hl * 8 + mtl) * 2 + ktl) * 128 + ln * 4), src);
            }
#pragma unroll
            for (int i = 0; i < 4; i++) {
                int slot = tid + i * 256;
                int hl = slot >> 9, ntl = (slot >> 5) & 15;
                int ktl = (slot >> 4) & 1, lp = slot & 15;
                const float* src = (hl ? Bfl : Bfh)
                    + ((size_t)((nt0 + ntl) * 64 + kt0 + ktl) * 32 + lp * 2) * 2;
                cp16(smem_u32(st + 4096 + ((hl * 16 + ntl) * 2 + ktl) * 64 + lp * 4), src);
            }
            cpcommit();
        };

        issue(0, 0);
        int s = 0;
        for (int ch = 0; ch < 32; ch++) {
            if (ch + 1 < 32) { issue(ch + 1, s ^ 1); cpwait<1>(); }
            else             { cpwait<0>(); }
            __syncthreads();
            const float* st = sm + s * 8192;
#pragma unroll
            for (int ktl = 0; ktl < 2; ktl++) {
                uint32_t ah[4][4], al[4][4], bh[4][2], bl[4][2];
#pragma unroll
                for (int mf = 0; mf < 4; mf++) {
                    int mtl = mw * 4 + mf;
                    *(float4*)&ah[mf][0] =
                        *(const float4*)(st + (mtl * 2 + ktl) * 128 + lane * 4);
                    *(float4*)&al[mf][0] =
                        *(const float4*)(st + ((8 + mtl) * 2 + ktl) * 128 + lane * 4);
                }
#pragma unroll
                for (int nf = 0; nf < 4; nf++) {
                    int ntl = nw * 4 + nf;
                    *(float2*)&bh[nf][0] =
                        *(const float2*)(st + 4096 + (ntl * 2 + ktl) * 64 + lane * 2);
                    *(float2*)&bl[nf][0] =
                        *(const float2*)(st + 4096 + ((16 + ntl) * 2 + ktl) * 64 + lane * 2);
                }
#pragma unroll
                for (int mf = 0; mf < 4; mf++)
#pragma unroll
                    for (int nf = 0; nf < 4; nf++) {
                        mma8(acc[mf][nf], ah[mf], bh[nf]);
                        mma8(acc[mf][nf], ah[mf], bl[nf]);
                        mma8(acc[mf][nf], al[mf], bh[nf]);
                    }
            }
            __syncthreads();
            s ^= 1;
        }

        // fold distances (codes ascending within a thread; strict < keeps first)
#pragma unroll
        for (int mf = 0; mf < 4; mf++)
#pragma unroll
            for (int half = 0; half < 2; half++) {
                int bslot = mf * 2 + half;
                float bs = bS[bslot];
                int   bi = bI[bslot];
#pragma unroll
                for (int nf = 0; nf < 4; nf++)
#pragma unroll
                    for (int r = 0; r < 2; r++) {
                        int col = vt + (nw * 4 + nf) * 8 + 2 * lc + r;
                        float d = fmaf(-2.f, acc[mf][nf][half * 2 + r],
                                       __ldg(&c2[col]));
                        if (d < bs) { bs = d; bi = col; }
                    }
                bS[bslot] = bs;
                bI[bslot] = bi;
            }
    }

    // cross-warp reduction (reuse smem stage 0): 16 contributors per row
    __syncthreads();
    float* redS = sm;                       // [128][17]
    int*   redI = (int*)(sm + 2176);        // [128][17]
#pragma unroll
    for (int mf = 0; mf < 4; mf++)
#pragma unroll
        for (int half = 0; half < 2; half++) {
            int row  = mw * 64 + mf * 16 + half * 8 + lr;
            int slot = nw * 4 + lc;
            redS[row * 17 + slot] = bS[mf * 2 + half];
            redI[row * 17 + slot] = bI[mf * 2 + half];
        }
    __syncthreads();
    if (tid < 128) {
        float bs = redS[tid * 17];
        int   bi = redI[tid * 17];
#pragma unroll
        for (int q = 1; q < 16; q++) {
            float v = redS[tid * 17 + q];
            int   i = redI[tid * 17 + q];
            if (v < bs || (v == bs && i < bi)) { bs = v; bi = i; }
        }
        partS[seg * 8192 + pt + tid] = bs;
        partI[seg * 8192 + pt + tid] = bi;
    }
}

// ---------------------------------------------------------------------------
// combine 8 segment partials + tokens; embedding gather
// ---------------------------------------------------------------------------
__global__ void __launch_bounds__(256) vq_final(
    const float* __restrict__ partS, const int* __restrict__ partI,
    int* __restrict__ tok, float* __restrict__ outTok, int writeTok)
{
    int pos = blockIdx.x * blockDim.x + threadIdx.x;
    if (pos >= 8192) return;
    float bs = partS[pos];
    int   bi = partI[pos];
#pragma unroll
    for (int s = 1; s < 8; s++) {
        float v = partS[s * 8192 + pos];
        int   i = partI[s * 8192 + pos];
        if (v < bs || (v == bs && i < bi)) { bs = v; bi = i; }
    }
    tok[pos] = bi;
    if (writeTok) outTok[pos] = (float)bi;
}

__global__ void __launch_bounds__(256) gather_kernel(
    const int* __restrict__ tok, const float* __restrict__ emb,
    float* __restrict__ out)
{
    size_t idx = (size_t)blockIdx.x * blockDim.x + threadIdx.x;
    int pos = (int)(idx >> 7);
    int c4  = (int)(idx & 127);
    float4 v = *(const float4*)&emb[(size_t)tok[pos] * 512 + c4 * 4];
    *(float4*)&out[(size_t)pos * 512 + c4 * 4] = v;
}

// ---------------------------------------------------------------------------
// launch (order puts conv2 in ncu's captured slot #4)
// ---------------------------------------------------------------------------
extern "C" void kernel_launch(void* const* d_in, const int* in_sizes, int n_in,
                              void* d_out, int out_size)
{
    const float* video = (const float*)d_in[0];
    const float* w1    = (const float*)d_in[1];
    const float* b1    = (const float*)d_in[2];
    const float* w2    = (const float*)d_in[3];
    const float* b2    = (const float*)d_in[4];
    const float* w3    = (const float*)d_in[5];
    const float* b3    = (const float*)d_in[6];
    const float* cb    = (const float*)d_in[7];
    const float* emb   = (const float*)d_in[8];

    float *h1, *h2, *ff, *afh, *afl, *bfh, *bfl, *c2, *ps;
    int *pi, *tk;
    cudaGetSymbolAddress((void**)&h1, g_h1);
    cudaGetSymbolAddress((void**)&h2, g_h2);
    cudaGetSymbolAddress((void**)&ff, g_f);
    cudaGetSymbolAddress((void**)&afh, g_Afh);
    cudaGetSymbolAddress((void**)&afl, g_Afl);
    cudaGetSymbolAddress((void**)&bfh, g_Bfh);
    cudaGetSymbolAddress((void**)&bfl, g_Bfl);
    cudaGetSymbolAddress((void**)&c2, g_c2);
    cudaGetSymbolAddress((void**)&ps, g_ps);
    cudaGetSymbolAddress((void**)&pi, g_pi);
    cudaGetSymbolAddress((void**)&tk, g_tok);

    cudaFuncSetAttribute(vq_frag_kernel,
                         cudaFuncAttributeMaxDynamicSharedMemorySize, VQ_SMEM);

    // 1: codebook split (ncu slot counting: 4th launch gets profiled)
    split_cb_kernel<<<256, 256>>>(cb, bfh, bfl);
    // 2: codebook norms
    c2_kernel<<<1024, 256>>>(cb, c2);
    // 3: conv1
    conv3d_kernel<3, 128, 16, 128, 128, 64, 64, true>
        <<<dim3(131072 / 128, 1), 256>>>(video, w1, b1, h1);
    // 4: conv2  <-- profiled
    conv3d_kernel<128, 256, 16, 64, 64, 32, 32, true>
        <<<dim3(32768 / 128, 2), 256>>>(h1, w2, b2, h2);
    // 5: conv3
    conv3d_kernel<256, 512, 16, 32, 32, 16, 16, false>
        <<<dim3(8192 / 128, 4), 256>>>(h2, w3, b3, ff);
    // 6: f split
    split_f_kernel<<<512, 256>>>(ff, afh, afl);
    // 7: VQ
    vq_frag_kernel<<<dim3(64, 8), 256, VQ_SMEM>>>(afh, afl, bfh, bfl, c2, ps, pi);

    float* outf = (float*)d_out;
    const int embElems = 8192 * 512;
    int writeTok = (out_size >= embElems + 8192) ? 1 : 0;
    float* embOut = outf + (writeTok ? 8192 : 0);

    // 8, 9
    vq_final<<<32, 256>>>(ps, pi, tk, outf, writeTok);
    gather_kernel<<<(8192 * 128) / 256, 256>>>(tk, emb, embOut);
}

// round 6
// speedup vs baseline: 2.4637x; 1.1117x over previous
#include <cuda_runtime.h>
#include <cstdint>
#include <cstddef>

// ---------------------------------------------------------------------------
// VideoEncoder: 3x Conv3D (stride 1,2,2; pad 1) + VQ argmin + embedding gather
// R6: two-pass VQ. Pass1 = single tf32 mma.sync (no split), best-2 per
//     (pos, 1024-code segment). Pass2 = exact fp32 re-score of <=16
//     candidates per position. Fragment prep fused into conv1/conv3.
// ---------------------------------------------------------------------------

__device__ float g_h1[2 * 128 * 16 * 64 * 64];   // 64 MB
__device__ float g_h2[2 * 256 * 16 * 32 * 32];   // 32 MB
__device__ float g_f [2 * 512 * 16 * 16 * 16];   // 16 MB
__device__ float g_Af[512 * 64 * 32 * 4];        // 16 MB  f  tf32 A-fragments
__device__ float g_Bf[1024 * 64 * 32 * 2];       // 16 MB  cb tf32 B-fragments
__device__ float g_c2[8192];
__device__ float g_ps[16 * 8192];
__device__ int   g_pi[16 * 8192];
__device__ int   g_tok[8192];

// ---------------------------------------------------------------------------
// helpers
// ---------------------------------------------------------------------------
__device__ __forceinline__ uint32_t smem_u32(const void* p) {
    uint32_t a;
    asm("{ .reg .u64 t; cvta.to.shared.u64 t, %1; cvt.u32.u64 %0, t; }"
        : "=r"(a) : "l"(p));
    return a;
}
__device__ __forceinline__ void cp16(uint32_t s, const void* g) {
    asm volatile("cp.async.cg.shared.global [%0], [%1], 16;" :: "r"(s), "l"(g));
}
__device__ __forceinline__ void cpcommit() {
    asm volatile("cp.async.commit_group;" ::: "memory");
}
template<int N> __device__ __forceinline__ void cpwait() {
    asm volatile("cp.async.wait_group %0;" :: "n"(N) : "memory");
}
__device__ __forceinline__ float tf32of(float x) {
    uint32_t b;
    asm("cvt.rna.tf32.f32 %0, %1;" : "=r"(b) : "f"(x));
    return __uint_as_float(b);
}
__device__ __forceinline__ void mma8(float* c, const uint32_t* a, const uint32_t* b) {
    asm volatile("mma.sync.aligned.m16n8k8.row.col.f32.tf32.tf32.f32 "
        "{%0,%1,%2,%3}, {%4,%5,%6,%7}, {%8,%9}, {%0,%1,%2,%3};"
        : "+f"(c[0]), "+f"(c[1]), "+f"(c[2]), "+f"(c[3])
        : "r"(a[0]), "r"(a[1]), "r"(a[2]), "r"(a[3]), "r"(b[0]), "r"(b[1]));
}

// ---------------------------------------------------------------------------
// conv3d scalar GEMM body (R2 microkernel). FSPLIT: also scatter tf32
// A-fragments of the output (conv3 -> VQ operand).
// ---------------------------------------------------------------------------
template<int CIN, int CO, int OT, int IH, int IW, int OH, int OW, bool RELU, bool FSPLIT>
__device__ __forceinline__ void conv3d_body(
    const float* __restrict__ x, const float* __restrict__ w,
    const float* __restrict__ bias, float* __restrict__ y,
    float* __restrict__ af, int bx, int by)
{
    constexpr int K   = CIN * 27;
    constexpr int IT  = OT;
    constexpr int SPO = OT * OH * OW;
    constexpr int NCH = (K + 15) / 16;

    __shared__ float Ws[16][128];
    __shared__ float Xs[16][128];

    const int tid = threadIdx.x;
    const int pt  = bx * 128;
    const int cot = by * 128;
    const int b   = pt / SPO;
    const int sp0 = pt - b * SPO;

    const int xk = tid >> 4;
    const int xp = (tid & 15) * 8;
    const int spx = sp0 + xp;
    const int t0  = spx / (OH * OW);
    const int rhw = spx % (OH * OW);
    const int h0  = rhw / OW;
    const int w0  = rhw % OW;
    const float* xb = x + (size_t)b * CIN * (IT * IH * IW);

    const int wc = tid >> 1;
    const int wk = (tid & 1) * 8;
    const float* wrow = w + (size_t)(cot + wc) * K;

    const int tr = tid >> 4;
    const int tc = tid & 15;

    float wbuf[8], xbuf[8];
    float acc[8][8];
#pragma unroll
    for (int i = 0; i < 8; i++)
#pragma unroll
        for (int j = 0; j < 8; j++) acc[i][j] = 0.f;

    auto loadW = [&](int k0) {
        if constexpr (K % 16 == 0) {
            float4 v0 = *(const float4*)(wrow + k0 + wk);
            float4 v1 = *(const float4*)(wrow + k0 + wk + 4);
            wbuf[0] = v0.x; wbuf[1] = v0.y; wbuf[2] = v0.z; wbuf[3] = v0.w;
            wbuf[4] = v1.x; wbuf[5] = v1.y; wbuf[6] = v1.z; wbuf[7] = v1.w;
        } else {
#pragma unroll
            for (int q = 0; q < 8; q++) {
                int k = k0 + wk + q;
                wbuf[q] = (k < K) ? wrow[k] : 0.f;
            }
        }
    };
    auto loadX = [&](int k0) {
        int k = k0 + xk;
        if constexpr (K % 16 != 0) {
            if (k >= K) {
#pragma unroll
                for (int q = 0; q < 8; q++) xbuf[q] = 0.f;
                return;
            }
        }
        int ci = k / 27, tap = k - ci * 27;
        int kt = tap / 9, r9 = tap - kt * 9;
        int kh = r9 / 3,  kw = r9 - kh * 3;
        int it  = t0 + kt - 1;
        int ih  = 2 * h0 + kh - 1;
        int iw0 = 2 * w0 + kw - 1;
        bool okp = ((unsigned)it < (unsigned)IT) && ((unsigned)ih < (unsigned)IH);
        const float* px = xb + ((size_t)ci * IT + it) * (IH * IW) + (long)ih * IW;
#pragma unroll
        for (int q = 0; q < 8; q++) {
            int iw = iw0 + 2 * q;
            bool ok = okp && ((unsigned)iw < (unsigned)IW);
            xbuf[q] = ok ? px[iw] : 0.f;
        }
    };

    loadW(0);
    loadX(0);

    for (int c0 = 0; c0 < NCH; c0++) {
        __syncthreads();
#pragma unroll
        for (int q = 0; q < 8; q++) Ws[wk + q][wc] = wbuf[q];
        *(float4*)&Xs[xk][xp]     = *(float4*)&xbuf[0];
        *(float4*)&Xs[xk][xp + 4] = *(float4*)&xbuf[4];
        __syncthreads();
        if (c0 + 1 < NCH) { loadW((c0 + 1) * 16); loadX((c0 + 1) * 16); }

#pragma unroll
        for (int kk = 0; kk < 16; kk++) {
            float a[8], bxr[8];
            *(float4*)&a[0]   = *(const float4*)&Ws[kk][tr * 8];
            *(float4*)&a[4]   = *(const float4*)&Ws[kk][tr * 8 + 4];
            *(float4*)&bxr[0] = *(const float4*)&Xs[kk][tc * 8];
            *(float4*)&bxr[4] = *(const float4*)&Xs[kk][tc * 8 + 4];
#pragma unroll
            for (int i = 0; i < 8; i++)
#pragma unroll
                for (int j = 0; j < 8; j++)
                    acc[i][j] = fmaf(a[i], bxr[j], acc[i][j]);
        }
    }

#pragma unroll
    for (int i = 0; i < 8; i++) {
        int co = cot + tr * 8 + i;
        float bv = bias[co];
        float o[8];
#pragma unroll
        for (int j = 0; j < 8; j++) {
            float v = acc[i][j] + bv;
            if (RELU) v = fmaxf(v, 0.f);
            o[j] = v;
        }
        float* yp = y + (size_t)(b * CO + co) * SPO + sp0 + tc * 8;
        *(float4*)yp       = *(float4*)&o[0];
        *(float4*)(yp + 4) = *(float4*)&o[4];
        if constexpr (FSPLIT) {
            // scatter tf32 A-fragments: pos = pt + tc*8 + j (global), c = co
            int kt = co >> 3, kc = co & 7;
            int lc = kc & 3, khalf = kc >> 2;
#pragma unroll
            for (int j = 0; j < 8; j++) {
                int pos = pt + tc * 8 + j;
                int r   = pos & 15;
                int lane = (r & 7) * 4 + lc;
                int q    = khalf * 2 + (r >> 3);
                af[((size_t)((pos >> 4) * 64 + kt) * 32 + lane) * 4 + q] = tf32of(o[j]);
            }
        }
    }
}

// conv2 (plain)
template<int CIN, int CO, int OT, int IH, int IW, int OH, int OW, bool RELU>
__global__ void __launch_bounds__(256, 2) conv3d_kernel(
    const float* __restrict__ x, const float* __restrict__ w,
    const float* __restrict__ bias, float* __restrict__ y)
{
    conv3d_body<CIN, CO, OT, IH, IW, OH, OW, RELU, false>(
        x, w, bias, y, nullptr, blockIdx.x, blockIdx.y);
}

// conv1 grid-fused with codebook fragment split + c2
__global__ void __launch_bounds__(256, 2) conv1_cb_kernel(
    const float* __restrict__ x, const float* __restrict__ w,
    const float* __restrict__ bias, float* __restrict__ y,
    const float* __restrict__ cb, float* __restrict__ bf, float* __restrict__ c2)
{
    if (blockIdx.x < 1024) {
        conv3d_body<3, 128, 16, 128, 128, 64, 64, true, false>(
            x, w, bias, y, nullptr, blockIdx.x, 0);
        return;
    }
    const int blk  = blockIdx.x - 1024;          // 0..255
    const int wid  = threadIdx.x >> 5;
    const int lane = threadIdx.x & 31;
    const int lr = lane >> 2, lc = lane & 3;
    // B-fragment split (tf32, single term)
    const int nt = blk * 4 + (wid & 3);
    const float* row = cb + (size_t)(nt * 8 + lr) * 512;
    for (int i = 0; i < 32; i++) {
        int kt = (wid >> 2) + 2 * i;
        float b0 = tf32of(row[kt * 8 + lc]);
        float b1 = tf32of(row[kt * 8 + lc + 4]);
        *(float2*)(bf + ((size_t)(nt * 64 + kt) * 32 + lane) * 2) = make_float2(b0, b1);
    }
    // c2 (bitwise-identical pattern to the original c2_kernel)
#pragma unroll
    for (int rr = 0; rr < 4; rr++) {
        int v = blk * 32 + wid * 4 + rr;
        const float* r = cb + (size_t)v * 512;
        float s = 0.f;
#pragma unroll 4
        for (int c = lane; c < 512; c += 32) { float xv = r[c]; s = fmaf(xv, xv, s); }
#pragma unroll
        for (int off = 16; off; off >>= 1) s += __shfl_down_sync(0xffffffffu, s, off);
        if (lane == 0) c2[v] = s;
    }
}

// conv3 with A-fragment scatter fused in epilogue
__global__ void __launch_bounds__(256, 2) conv3_fs_kernel(
    const float* __restrict__ x, const float* __restrict__ w,
    const float* __restrict__ bias, float* __restrict__ y, float* __restrict__ af)
{
    conv3d_body<256, 512, 16, 32, 32, 16, 16, false, true>(
        x, w, bias, y, af, blockIdx.x, blockIdx.y);
}

// ---------------------------------------------------------------------------
// Pass 1: single-MMA tf32 approx distances, best-2 per (pos, segment).
// grid (64 pos-tiles, 8 segments), 256 threads, 32 KB dynamic smem.
//   stage (4096 floats): A [mtl(8)][ktl(2)][128], B at +2048 [ntl(16)][ktl(2)][64]
// ---------------------------------------------------------------------------
static constexpr int P1_SMEM = 2 * 4096 * 4;   // 32 KB

__global__ void __launch_bounds__(256) vq_p1_kernel(
    const float* __restrict__ Af, const float* __restrict__ Bf,
    const float* __restrict__ c2,
    float* __restrict__ partS, int* __restrict__ partI)
{
    extern __shared__ float sm[];

    const int tid  = threadIdx.x;
    const int wid  = tid >> 5;
    const int lane = tid & 31;
    const int lr   = lane >> 2, lc = lane & 3;
    const int mw   = wid >> 2,  nw = wid & 3;

    const int pt  = blockIdx.x * 128;
    const int seg = blockIdx.y;
    const int mt0 = blockIdx.x * 8;

    float s1[8], s2[8];
    int   i1[8], i2[8];
#pragma unroll
    for (int i = 0; i < 8; i++) { s1[i] = 3.4e38f; s2[i] = 3.4e38f; i1[i] = 0; i2[i] = 0; }

    for (int tile = 0; tile < 8; tile++) {
        const int nt0 = seg * 128 + tile * 16;
        const int vt  = seg * 1024 + tile * 128;

        float acc[4][4][4];
#pragma unroll
        for (int a = 0; a < 4; a++)
#pragma unroll
            for (int c = 0; c < 4; c++)
#pragma unroll
                for (int r = 0; r < 4; r++) acc[a][c][r] = 0.f;

        auto issue = [&](int ch, int s) {
            float* st = sm + s * 4096;
            const int kt0 = ch * 2;
#pragma unroll
            for (int i = 0; i < 2; i++) {
                int slot = tid + i * 256;      // 512 slots for A
                int mtl = slot >> 6, ktl = (slot >> 5) & 1, ln = slot & 31;
                cp16(smem_u32(st + (mtl * 2 + ktl) * 128 + ln * 4),
                     Af + ((size_t)((mt0 + mtl) * 64 + kt0 + ktl) * 32 + ln) * 4);
            }
#pragma unroll
            for (int i = 0; i < 2; i++) {
                int slot = tid + i * 256;      // 512 slots for B
                int ntl = slot >> 5, ktl = (slot >> 4) & 1, lp = slot & 15;
                cp16(smem_u32(st + 2048 + (ntl * 2 + ktl) * 64 + lp * 4),
                     Bf + ((size_t)((nt0 + ntl) * 64 + kt0 + ktl) * 32 + lp * 2) * 2);
            }
            cpcommit();
        };

        issue(0, 0);
        int s = 0;
        for (int ch = 0; ch < 32; ch++) {
            if (ch + 1 < 32) { issue(ch + 1, s ^ 1); cpwait<1>(); }
            else             { cpwait<0>(); }
            __syncthreads();
            const float* st = sm + s * 4096;
#pragma unroll
            for (int ktl = 0; ktl < 2; ktl++) {
                uint32_t ah[4][4], bh[4][2];
#pragma unroll
                for (int mf = 0; mf < 4; mf++)
                    *(float4*)&ah[mf][0] = *(const float4*)(
                        st + ((mw * 4 + mf) * 2 + ktl) * 128 + lane * 4);
#pragma unroll
                for (int nf = 0; nf < 4; nf++)
                    *(float2*)&bh[nf][0] = *(const float2*)(
                        st + 2048 + ((nw * 4 + nf) * 2 + ktl) * 64 + lane * 2);
#pragma unroll
                for (int mf = 0; mf < 4; mf++)
#pragma unroll
                    for (int nf = 0; nf < 4; nf++)
                        mma8(acc[mf][nf], ah[mf], bh[nf]);
            }
            __syncthreads();
            s ^= 1;
        }

        // fold best-2 per row-slot
#pragma unroll
        for (int mf = 0; mf < 4; mf++)
#pragma unroll
            for (int half = 0; half < 2; half++) {
                int bs = mf * 2 + half;
#pragma unroll
                for (int nf = 0; nf < 4; nf++)
#pragma unroll
                    for (int r = 0; r < 2; r++) {
                        int col = vt + (nw * 4 + nf) * 8 + 2 * lc + r;
                        float d = fmaf(-2.f, acc[mf][nf][half * 2 + r],
                                       __ldg(&c2[col]));
                        if (d < s1[bs]) {
                            s2[bs] = s1[bs]; i2[bs] = i1[bs];
                            s1[bs] = d;      i1[bs] = col;
                        } else if (d < s2[bs]) {
                            s2[bs] = d;      i2[bs] = col;
                        }
                    }
            }
    }

    // reduction: 16 contributors x best-2 per row
    __syncthreads();
    float* redS = sm;                 // [128][32]
    int*   redI = (int*)(sm + 4096);  // [128][32]
#pragma unroll
    for (int mf = 0; mf < 4; mf++)
#pragma unroll
        for (int half = 0; half < 2; half++) {
            int bs   = mf * 2 + half;
            int row  = mw * 64 + mf * 16 + half * 8 + lr;
            int cont = nw * 4 + lc;
            redS[row * 32 + cont * 2]     = s1[bs];
            redS[row * 32 + cont * 2 + 1] = s2[bs];
            redI[row * 32 + cont * 2]     = i1[bs];
            redI[row * 32 + cont * 2 + 1] = i2[bs];
        }
    __syncthreads();
    if (tid < 128) {
        float b1 = 3.4e38f, b2 = 3.4e38f;
        int   j1 = 0, j2 = 0;
#pragma unroll
        for (int q = 0; q < 32; q++) {
            float v = redS[tid * 32 + q];
            int   i = redI[tid * 32 + q];
            if (v < b1) { b2 = b1; j2 = j1; b1 = v; j1 = i; }
            else if (v < b2) { b2 = v; j2 = i; }
        }
        int pos = pt + tid;
        partS[(seg * 2 + 0) * 8192 + pos] = b1;
        partI[(seg * 2 + 0) * 8192 + pos] = j1;
        partS[(seg * 2 + 1) * 8192 + pos] = b2;
        partI[(seg * 2 + 1) * 8192 + pos] = j2;
    }
}

// ---------------------------------------------------------------------------
// Pass 2: exact fp32 re-score of 16 candidates per position. One warp/pos.
// ---------------------------------------------------------------------------
__global__ void __launch_bounds__(256) vq_p2_kernel(
    const float* __restrict__ f, const float* __restrict__ cb,
    const int* __restrict__ partI,
    int* __restrict__ tok, float* __restrict__ outTok, int writeTok)
{
    const int wid  = threadIdx.x >> 5;
    const int lane = threadIdx.x & 31;
    const int pos  = blockIdx.x * 8 + wid;
    const int b    = pos >> 12;
    const int sp   = pos & 4095;

    float fv[16];
#pragma unroll
    for (int t = 0; t < 16; t++)
        fv[t] = f[((size_t)b * 512 + lane + 32 * t) * 4096 + sp];

    float best = 3.4e38f;
    int   bi   = 0x7fffffff;
#pragma unroll 1
    for (int j = 0; j < 16; j++) {
        int v = partI[j * 8192 + pos];
        const float* cr = cb + (size_t)v * 512;
        float dot = 0.f, cc = 0.f;
#pragma unroll
        for (int t = 0; t < 16; t++) {
            float cv = cr[lane + 32 * t];
            dot = fmaf(fv[t], cv, dot);
            cc  = fmaf(cv, cv, cc);
        }
#pragma unroll
        for (int off = 16; off; off >>= 1) {
            dot += __shfl_down_sync(0xffffffffu, dot, off);
            cc  += __shfl_down_sync(0xffffffffu, cc,  off);
        }
        if (lane == 0) {
            float d = fmaf(-2.f, dot, cc);
            if (d < best || (d == best && v < bi)) { best = d; bi = v; }
        }
    }
    if (lane == 0) {
        tok[pos] = bi;
        if (writeTok) outTok[pos] = (float)bi;
    }
}

// embeddings = emb_table[tokens]
__global__ void __launch_bounds__(256) gather_kernel(
    const int* __restrict__ tok, const float* __restrict__ emb,
    float* __restrict__ out)
{
    size_t idx = (size_t)blockIdx.x * blockDim.x + threadIdx.x;
    int pos = (int)(idx >> 7);
    int c4  = (int)(idx & 127);
    float4 v = *(const float4*)&emb[(size_t)tok[pos] * 512 + c4 * 4];
    *(float4*)&out[(size_t)pos * 512 + c4 * 4] = v;
}

// ---------------------------------------------------------------------------
// launch (vq_p1 is the 4th launch -> profiled by ncu)
// ---------------------------------------------------------------------------
extern "C" void kernel_launch(void* const* d_in, const int* in_sizes, int n_in,
                              void* d_out, int out_size)
{
    const float* video = (const float*)d_in[0];
    const float* w1    = (const float*)d_in[1];
    const float* b1    = (const float*)d_in[2];
    const float* w2    = (const float*)d_in[3];
    const float* b2    = (const float*)d_in[4];
    const float* w3    = (const float*)d_in[5];
    const float* b3    = (const float*)d_in[6];
    const float* cb    = (const float*)d_in[7];
    const float* emb   = (const float*)d_in[8];

    float *h1, *h2, *ff, *af, *bf, *c2, *ps;
    int *pi, *tk;
    cudaGetSymbolAddress((void**)&h1, g_h1);
    cudaGetSymbolAddress((void**)&h2, g_h2);
    cudaGetSymbolAddress((void**)&ff, g_f);
    cudaGetSymbolAddress((void**)&af, g_Af);
    cudaGetSymbolAddress((void**)&bf, g_Bf);
    cudaGetSymbolAddress((void**)&c2, g_c2);
    cudaGetSymbolAddress((void**)&ps, g_ps);
    cudaGetSymbolAddress((void**)&pi, g_pi);
    cudaGetSymbolAddress((void**)&tk, g_tok);

    cudaFuncSetAttribute(vq_p1_kernel,
                         cudaFuncAttributeMaxDynamicSharedMemorySize, P1_SMEM);

    // 1: conv1 + codebook fragment split + c2
    conv1_cb_kernel<<<1024 + 256, 256>>>(video, w1, b1, h1, cb, bf, c2);
    // 2: conv2
    conv3d_kernel<128, 256, 16, 64, 64, 32, 32, true>
        <<<dim3(256, 2), 256>>>(h1, w2, b2, h2);
    // 3: conv3 + f fragment scatter
    conv3_fs_kernel<<<dim3(64, 4), 256>>>(h2, w3, b3, ff, af);
    // 4: VQ pass 1 (profiled)
    vq_p1_kernel<<<dim3(64, 8), 256, P1_SMEM>>>(af, bf, c2, ps, pi);

    float* outf = (float*)d_out;
    const int embElems = 8192 * 512;
    int writeTok = (out_size >= embElems + 8192) ? 1 : 0;
    float* embOut = outf + (writeTok ? 8192 : 0);

    // 5: VQ pass 2 (exact re-score, tokens)
    vq_p2_kernel<<<1024, 256>>>(ff, cb, pi, tk, outf, writeTok);
    // 6: embedding gather
    gather_kernel<<<(8192 * 128) / 256, 256>>>(tk, emb, embOut);
}